// round 15
// baseline (speedup 1.0000x reference)
#include <cuda_runtime.h>
#include <cuda_bf16.h>
#include <cfloat>
#include <cstdint>

#define N_EMBED  8192
#define E_DIM    64
#define N_QUERY  16384
#define MT       128                 // queries per CTA
#define NQUART   (N_EMBED / 4)       // codes per warp-group quarter (2048)
#define NCHUNK_Q (NQUART / 16)       // 128 chunks of 16 codes
#define CAND_MAX 160
#define MARGIN   0.5f

// ---------------- global scratch ----------------
__device__ __align__(16) float g_norms[N_EMBED];
__device__ __align__(16) float g_embT [N_EMBED * E_DIM];   // [code][k] fp32 (rescore)
__device__ __align__(16) float g_xq   [N_QUERY * E_DIM];   // [q][k] fp32 (rescore)
// MMA-fragment-interleaved operands (built by prep):
//   bfrag2[nb][kp][lane] = uint4 {b0(ks),b1(ks),b0(ks+1),b1(ks+1)}, ks = 2*kp
//   nfrag [ch][lane]     = float4 norms a lane needs for 16-code chunk ch
//   afrag [qb][ks][lane] = uint4 A fragment for 16-query block qb
__device__ __align__(16) uint4  g_bfrag2[N_EMBED / 8][2][32];
__device__ __align__(16) float4 g_nfrag [N_EMBED / 16][32];
__device__ __align__(16) uint4  g_afrag [N_QUERY / 16][4][32];
__device__ int g_cand [N_QUERY * CAND_MAX];
__device__ int g_ncand[N_QUERY];

__device__ __forceinline__ void mma16816(float* c, const uint32_t* a,
                                         uint32_t b0, uint32_t b1) {
    asm volatile(
        "mma.sync.aligned.m16n8k16.row.col.f32.bf16.bf16.f32 "
        "{%0,%1,%2,%3}, {%4,%5,%6,%7}, {%8,%9}, {%0,%1,%2,%3};"
        : "+f"(c[0]), "+f"(c[1]), "+f"(c[2]), "+f"(c[3])
        : "r"(a[0]), "r"(a[1]), "r"(a[2]), "r"(a[3]), "r"(b0), "r"(b1));
}

__device__ __forceinline__ uint32_t pack_bf(float lo, float hi) {
    __nv_bfloat16 l = __float2bfloat16(lo), h = __float2bfloat16(hi);
    return (uint32_t)__bfloat16_as_ushort(l) | ((uint32_t)__bfloat16_as_ushort(h) << 16);
}

// ---------------- fused prep kernel ----------------
__global__ void __launch_bounds__(256) prep_kernel(const float* __restrict__ x,
                                                   const float* __restrict__ embed) {
    const int bid = blockIdx.x;
    const int t = threadIdx.x;
    __shared__ float s[64][33];
    __shared__ float nsh[32];

    if (bid < 256) {                                     // 32 codes per block
        const int j0 = bid * 32;
#pragma unroll
        for (int it = 0; it < 8; ++it) {
            int idx = t + it * 256;
            int d = idx >> 5, jj = idx & 31;
            s[d][jj] = embed[d * N_EMBED + j0 + jj];
        }
        __syncthreads();
#pragma unroll
        for (int it = 0; it < 8; ++it) {
            int idx = t + it * 256;
            int jj = idx >> 6, d = idx & 63;
            g_embT[(j0 + jj) * E_DIM + d] = s[d][jj];
        }
        if (t < 32) {
            float sum = 0.f;
#pragma unroll
            for (int d = 0; d < E_DIM; ++d) { float v = s[d][t]; sum = fmaf(v, v, sum); }
            nsh[t] = sum;
            g_norms[j0 + t] = sum;
        }
        // B fragments, ks-paired: 4 nb x 2 kp x 32 lanes = 256 uint4, one per thread
        {
            int lane = t & 31, grp = t >> 5;
            int lnb = grp & 3, kp = grp >> 2;
            int jl = lnb * 8 + (lane >> 2);
            int kb = kp * 32 + (lane & 3) * 2;
            uint4 v;
            v.x = pack_bf(s[kb][jl],      s[kb + 1][jl]);
            v.y = pack_bf(s[kb + 8][jl],  s[kb + 9][jl]);
            v.z = pack_bf(s[kb + 16][jl], s[kb + 17][jl]);
            v.w = pack_bf(s[kb + 24][jl], s[kb + 25][jl]);
            g_bfrag2[bid * 4 + lnb][kp][lane] = v;
        }
        __syncthreads();
        // norm fragments: 2 chunk16s x 32 lanes
        if (t < 64) {
            int lane = t & 31;
            int lb = (t >> 5) * 16;
            int kc = (lane & 3) * 2;
            float4 v;
            v.x = nsh[lb + kc];     v.y = nsh[lb + kc + 1];
            v.z = nsh[lb + 8 + kc]; v.w = nsh[lb + 8 + kc + 1];
            g_nfrag[bid * 2 + (t >> 5)][lane] = v;
        }
    } else {                                             // 32 queries per block
        const int q0 = (bid - 256) * 32;
        const int gt = (bid - 256) * 256 + t;
        if (gt < N_QUERY) g_ncand[gt] = 0;
        const int b = q0 >> 10, hw0 = q0 & 1023;
#pragma unroll
        for (int it = 0; it < 8; ++it) {
            int idx = t + it * 256;
            int d = idx >> 5, qq = idx & 31;
            s[d][qq] = x[b * 65536 + d * 1024 + hw0 + qq];
        }
        __syncthreads();
#pragma unroll
        for (int it = 0; it < 8; ++it) {
            int idx = t + it * 256;
            int qq = idx >> 6, d = idx & 63;
            g_xq[(q0 + qq) * E_DIM + d] = s[d][qq];
        }
        {
            int lane = t & 31, grp = t >> 5;
            int lqb = grp & 1, ks = grp >> 1;
            int r = lqb * 16 + (lane >> 2);
            int kb = ks * 16 + (lane & 3) * 2;
            uint4 v;
            v.x = pack_bf(s[kb][r],         s[kb + 1][r]);
            v.y = pack_bf(s[kb][r + 8],     s[kb + 1][r + 8]);
            v.z = pack_bf(s[kb + 8][r],     s[kb + 9][r]);
            v.w = pack_bf(s[kb + 8][r + 8], s[kb + 9][r + 8]);
            g_afrag[(bid - 256) * 2 + lqb][ks][lane] = v;
        }
    }
}

// ---------------- main kernel: 32 q/warp, 16-code chunks, LDG.128 fragments ------
// 16 warps: wg = wid>>2 (code quarter), wl = wid&3 (32-query m-block).
// 4 warps per quarter walk the SAME stream -> L1 serves 3/4 of B reads.
__global__ void __launch_bounds__(512, 1) vq_mma_kernel() {
    const int tid  = threadIdx.x;
    const int lane = tid & 31;
    const int wid  = tid >> 5;
    const int wg   = wid >> 2;           // code quarter
    const int wl   = wid & 3;            // 32-query m-block
    const int q0   = blockIdx.x * MT + wl * 32;
    const int qb   = blockIdx.x * 8 + wl * 2;
    const int kc   = (lane & 3) * 2;
    const int rbase = q0 + (lane >> 2);

    uint4 af[2][4];
#pragma unroll
    for (int mi = 0; mi < 2; ++mi)
#pragma unroll
        for (int ks = 0; ks < 4; ++ks)
            af[mi][ks] = g_afrag[qb + mi][ks][lane];

    // chunk c, block nt, pair kp at bbase[c*128 + nt*64 + kp*32]
    const uint4*  bbase = &g_bfrag2[wg * (NQUART / 8)][0][lane];
    const float4* nbase_p = &g_nfrag[wg * (NQUART / 16)][lane];
    const int nbase = wg * NQUART;

    float runbest[4] = {FLT_MAX, FLT_MAX, FLT_MAX, FLT_MAX};

    // ---- warmup: chunk 0, min-only ----
    {
        uint4 wb[2][2];                  // [nt][kp]
#pragma unroll
        for (int nt = 0; nt < 2; ++nt)
#pragma unroll
            for (int kp = 0; kp < 2; ++kp)
                wb[nt][kp] = bbase[nt * 64 + kp * 32];
        float4 nf = nbase_p[0];
        float acc[2][2][4];
#pragma unroll
        for (int mi = 0; mi < 2; ++mi)
#pragma unroll
            for (int nt = 0; nt < 2; ++nt)
#pragma unroll
                for (int e = 0; e < 4; ++e) acc[mi][nt][e] = 0.f;
#pragma unroll
        for (int kp = 0; kp < 2; ++kp)
#pragma unroll
            for (int mi = 0; mi < 2; ++mi)
#pragma unroll
                for (int nt = 0; nt < 2; ++nt) {
                    mma16816(acc[mi][nt], (const uint32_t*)&af[mi][kp * 2],
                             wb[nt][kp].x, wb[nt][kp].y);
                    mma16816(acc[mi][nt], (const uint32_t*)&af[mi][kp * 2 + 1],
                             wb[nt][kp].z, wb[nt][kp].w);
                }
#pragma unroll
        for (int mi = 0; mi < 2; ++mi)
#pragma unroll
            for (int rr = 0; rr < 2; ++rr) {
                float gm = fminf(
                    fminf(fmaf(-2.f, acc[mi][0][rr * 2],     nf.x),
                          fmaf(-2.f, acc[mi][0][rr * 2 + 1], nf.y)),
                    fminf(fmaf(-2.f, acc[mi][1][rr * 2],     nf.z),
                          fmaf(-2.f, acc[mi][1][rr * 2 + 1], nf.w)));
                runbest[mi * 2 + rr] = gm;
            }
#pragma unroll
        for (int s2 = 0; s2 < 4; ++s2) {
            runbest[s2] = fminf(runbest[s2], __shfl_xor_sync(0xFFFFFFFFu, runbest[s2], 1));
            runbest[s2] = fminf(runbest[s2], __shfl_xor_sync(0xFFFFFFFFu, runbest[s2], 2));
        }
    }

    // ---- pipelined main loop: ping-pong ring over ks-pairs ----
    uint4 ring[2][2];                    // [slot][nt]
#pragma unroll
    for (int nt = 0; nt < 2; ++nt)       // prologue: kp0(chunk0), L1-hot
        ring[0][nt] = bbase[nt * 64];

#pragma unroll 1
    for (int c = 0; c < NCHUNK_Q; ++c) {
        const uint4* bc  = bbase + c * 128;
        const uint4* bcn = (c + 1 < NCHUNK_Q) ? bc + 128 : bc;

        float acc[2][2][4];
#pragma unroll
        for (int mi = 0; mi < 2; ++mi)
#pragma unroll
            for (int nt = 0; nt < 2; ++nt)
#pragma unroll
                for (int e = 0; e < 4; ++e) acc[mi][nt][e] = 0.f;

        // phase A: prefetch kp1(c) -> slot1; load norms; MMA slot0 (ks0, ks1)
#pragma unroll
        for (int nt = 0; nt < 2; ++nt) ring[1][nt] = bc[nt * 64 + 32];
        float4 nf = nbase_p[c * 32];
#pragma unroll
        for (int mi = 0; mi < 2; ++mi)
#pragma unroll
            for (int nt = 0; nt < 2; ++nt) {
                mma16816(acc[mi][nt], (const uint32_t*)&af[mi][0],
                         ring[0][nt].x, ring[0][nt].y);
                mma16816(acc[mi][nt], (const uint32_t*)&af[mi][1],
                         ring[0][nt].z, ring[0][nt].w);
            }

        // phase B: prefetch kp0(c+1) -> slot0; MMA slot1 (ks2, ks3)
#pragma unroll
        for (int nt = 0; nt < 2; ++nt) ring[0][nt] = bcn[nt * 64];
#pragma unroll
        for (int mi = 0; mi < 2; ++mi)
#pragma unroll
            for (int nt = 0; nt < 2; ++nt) {
                mma16816(acc[mi][nt], (const uint32_t*)&af[mi][2],
                         ring[1][nt].x, ring[1][nt].y);
                mma16816(acc[mi][nt], (const uint32_t*)&af[mi][3],
                         ring[1][nt].z, ring[1][nt].w);
            }

        // ---- group-min epilogue (16 scores) ----
        const int cb = nbase + c * 16;
#pragma unroll
        for (int mi = 0; mi < 2; ++mi)
#pragma unroll
            for (int rr = 0; rr < 2; ++rr) {
                const int i = mi * 2 + rr;
                float s0 = fmaf(-2.f, acc[mi][0][rr * 2],     nf.x);
                float s1 = fmaf(-2.f, acc[mi][0][rr * 2 + 1], nf.y);
                float s2 = fmaf(-2.f, acc[mi][1][rr * 2],     nf.z);
                float s3 = fmaf(-2.f, acc[mi][1][rr * 2 + 1], nf.w);
                float gm = fminf(fminf(s0, s1), fminf(s2, s3));
                const float th = runbest[i] + MARGIN;
                if (gm < th) {                          // rare
                    const int q = rbase + mi * 16 + rr * 8;
                    if (s0 < th) {
                        int pos = atomicAdd(&g_ncand[q], 1);
                        if (pos < CAND_MAX) g_cand[q * CAND_MAX + pos] = cb + kc;
                    }
                    if (s1 < th) {
                        int pos = atomicAdd(&g_ncand[q], 1);
                        if (pos < CAND_MAX) g_cand[q * CAND_MAX + pos] = cb + kc + 1;
                    }
                    if (s2 < th) {
                        int pos = atomicAdd(&g_ncand[q], 1);
                        if (pos < CAND_MAX) g_cand[q * CAND_MAX + pos] = cb + 8 + kc;
                    }
                    if (s3 < th) {
                        int pos = atomicAdd(&g_ncand[q], 1);
                        if (pos < CAND_MAX) g_cand[q * CAND_MAX + pos] = cb + 8 + kc + 1;
                    }
                }
                runbest[i] = fminf(runbest[i], gm);
            }
#pragma unroll
        for (int s2 = 0; s2 < 4; ++s2) {
            runbest[s2] = fminf(runbest[s2], __shfl_xor_sync(0xFFFFFFFFu, runbest[s2], 1));
            runbest[s2] = fminf(runbest[s2], __shfl_xor_sync(0xFFFFFFFFu, runbest[s2], 2));
        }
    }
}

// ---------------- exact fp32 rescore + gather (candidate-per-lane) ----------------
__global__ void __launch_bounds__(256) rescore_kernel(float* __restrict__ out) {
    const int wid = threadIdx.x >> 5, lane = threadIdx.x & 31;
    const int q = blockIdx.x * 8 + wid;

    const float4* xr = (const float4*)(g_xq + (size_t)q * E_DIM);
    const int nc = g_ncand[q];

    float best = FLT_MAX;
    int bj = N_EMBED;

    if (nc <= CAND_MAX) {
        for (int base = 0; base < nc; base += 32) {
            int i = base + lane;
            float s = FLT_MAX;
            int j = N_EMBED;
            if (i < nc) {
                j = g_cand[q * CAND_MAX + i];
                const float4* er = (const float4*)(g_embT + (size_t)j * E_DIM);
                float p = 0.f;
#pragma unroll
                for (int t = 0; t < 16; ++t) {
                    float4 e = er[t], xx = xr[t];
                    p = fmaf(e.x, xx.x, p); p = fmaf(e.y, xx.y, p);
                    p = fmaf(e.z, xx.z, p); p = fmaf(e.w, xx.w, p);
                }
                s = fmaf(-2.f, p, g_norms[j]);
            }
            if (s < best || (s == best && j < bj)) { best = s; bj = j; }
        }
    } else {
        for (int j0 = 0; j0 < N_EMBED; j0 += 32) {     // overflow fallback (rare)
            int j = j0 + lane;
            const float4* er = (const float4*)(g_embT + (size_t)j * E_DIM);
            float p = 0.f;
#pragma unroll
            for (int t = 0; t < 16; ++t) {
                float4 e = er[t], xx = xr[t];
                p = fmaf(e.x, xx.x, p); p = fmaf(e.y, xx.y, p);
                p = fmaf(e.z, xx.z, p); p = fmaf(e.w, xx.w, p);
            }
            float s = fmaf(-2.f, p, g_norms[j]);
            if (s < best || (s == best && j < bj)) { best = s; bj = j; }
        }
    }

#pragma unroll
    for (int off = 16; off > 0; off >>= 1) {
        float os = __shfl_xor_sync(0xFFFFFFFFu, best, off);
        int   oj = __shfl_xor_sync(0xFFFFFFFFu, bj, off);
        if (os < best || (os == best && oj < bj)) { best = os; bj = oj; }
    }

    out[(size_t)q * E_DIM + lane]      = g_embT[(size_t)bj * E_DIM + lane];
    out[(size_t)q * E_DIM + 32 + lane] = g_embT[(size_t)bj * E_DIM + 32 + lane];
}

// ---------------- launch ----------------
extern "C" void kernel_launch(void* const* d_in, const int* in_sizes, int n_in,
                              void* d_out, int out_size) {
    const float* x     = (const float*)d_in[0];   // [16,64,32,32]
    const float* embed = (const float*)d_in[1];   // [64,8192]
    float* out = (float*)d_out;                   // [16,32,32,64]

    prep_kernel<<<768, 256>>>(x, embed);
    vq_mma_kernel<<<N_QUERY / MT, 512>>>();
    rescore_kernel<<<N_QUERY / 8, 256>>>(out);
}

// round 16
// speedup vs baseline: 1.0116x; 1.0116x over previous
#include <cuda_runtime.h>
#include <cuda_bf16.h>
#include <cfloat>
#include <cstdint>

#define N_EMBED  8192
#define E_DIM    64
#define N_QUERY  16384
#define MT       128                 // queries per CTA
#define NQUART   (N_EMBED / 4)       // codes per warp-group quarter (2048)
#define NCHUNK_Q (NQUART / 16)       // 128 chunks of 16 codes
#define CAND_MAX 160
#define MARGIN   0.5f

// ---------------- global scratch ----------------
__device__ __align__(16) float g_norms[N_EMBED];
__device__ __align__(16) float g_embT [N_EMBED * E_DIM];   // [code][k] fp32 (rescore)
__device__ __align__(16) float g_xq   [N_QUERY * E_DIM];   // [q][k] fp32 (rescore)
// MMA-fragment-interleaved operands (built by prep):
//   bfrag2[nb][kp][lane] = uint4 {b0(ks),b1(ks),b0(ks+1),b1(ks+1)}, ks = 2*kp
//   nfrag [ch][lane]     = float4 norms a lane needs for 16-code chunk ch
//   afrag [qb][ks][lane] = uint4 A fragment for 16-query block qb
__device__ __align__(16) uint4  g_bfrag2[N_EMBED / 8][2][32];
__device__ __align__(16) float4 g_nfrag [N_EMBED / 16][32];
__device__ __align__(16) uint4  g_afrag [N_QUERY / 16][4][32];
__device__ int g_cand [N_QUERY * CAND_MAX];
__device__ int g_ncand[N_QUERY];

__device__ __forceinline__ void mma16816(float* c, const uint32_t* a,
                                         uint32_t b0, uint32_t b1) {
    asm volatile(
        "mma.sync.aligned.m16n8k16.row.col.f32.bf16.bf16.f32 "
        "{%0,%1,%2,%3}, {%4,%5,%6,%7}, {%8,%9}, {%0,%1,%2,%3};"
        : "+f"(c[0]), "+f"(c[1]), "+f"(c[2]), "+f"(c[3])
        : "r"(a[0]), "r"(a[1]), "r"(a[2]), "r"(a[3]), "r"(b0), "r"(b1));
}

__device__ __forceinline__ uint32_t pack_bf(float lo, float hi) {
    __nv_bfloat16 l = __float2bfloat16(lo), h = __float2bfloat16(hi);
    return (uint32_t)__bfloat16_as_ushort(l) | ((uint32_t)__bfloat16_as_ushort(h) << 16);
}

// ---------------- fused prep kernel ----------------
__global__ void __launch_bounds__(256) prep_kernel(const float* __restrict__ x,
                                                   const float* __restrict__ embed) {
    const int bid = blockIdx.x;
    const int t = threadIdx.x;
    __shared__ float s[64][33];
    __shared__ float nsh[32];

    if (bid < 256) {                                     // 32 codes per block
        const int j0 = bid * 32;
#pragma unroll
        for (int it = 0; it < 8; ++it) {
            int idx = t + it * 256;
            int d = idx >> 5, jj = idx & 31;
            s[d][jj] = embed[d * N_EMBED + j0 + jj];
        }
        __syncthreads();
#pragma unroll
        for (int it = 0; it < 8; ++it) {
            int idx = t + it * 256;
            int jj = idx >> 6, d = idx & 63;
            g_embT[(j0 + jj) * E_DIM + d] = s[d][jj];
        }
        if (t < 32) {
            float sum = 0.f;
#pragma unroll
            for (int d = 0; d < E_DIM; ++d) { float v = s[d][t]; sum = fmaf(v, v, sum); }
            nsh[t] = sum;
            g_norms[j0 + t] = sum;
        }
        // B fragments, ks-paired: 4 nb x 2 kp x 32 lanes = 256 uint4, one per thread
        {
            int lane = t & 31, grp = t >> 5;
            int lnb = grp & 3, kp = grp >> 2;
            int jl = lnb * 8 + (lane >> 2);
            int kb = kp * 32 + (lane & 3) * 2;
            uint4 v;
            v.x = pack_bf(s[kb][jl],      s[kb + 1][jl]);
            v.y = pack_bf(s[kb + 8][jl],  s[kb + 9][jl]);
            v.z = pack_bf(s[kb + 16][jl], s[kb + 17][jl]);
            v.w = pack_bf(s[kb + 24][jl], s[kb + 25][jl]);
            g_bfrag2[bid * 4 + lnb][kp][lane] = v;
        }
        __syncthreads();
        // norm fragments: 2 chunk16s x 32 lanes
        if (t < 64) {
            int lane = t & 31;
            int lb = (t >> 5) * 16;
            int kc = (lane & 3) * 2;
            float4 v;
            v.x = nsh[lb + kc];     v.y = nsh[lb + kc + 1];
            v.z = nsh[lb + 8 + kc]; v.w = nsh[lb + 8 + kc + 1];
            g_nfrag[bid * 2 + (t >> 5)][lane] = v;
        }
    } else {                                             // 32 queries per block
        const int q0 = (bid - 256) * 32;
        const int gt = (bid - 256) * 256 + t;
        if (gt < N_QUERY) g_ncand[gt] = 0;
        const int b = q0 >> 10, hw0 = q0 & 1023;
#pragma unroll
        for (int it = 0; it < 8; ++it) {
            int idx = t + it * 256;
            int d = idx >> 5, qq = idx & 31;
            s[d][qq] = x[b * 65536 + d * 1024 + hw0 + qq];
        }
        __syncthreads();
#pragma unroll
        for (int it = 0; it < 8; ++it) {
            int idx = t + it * 256;
            int qq = idx >> 6, d = idx & 63;
            g_xq[(q0 + qq) * E_DIM + d] = s[d][qq];
        }
        {
            int lane = t & 31, grp = t >> 5;
            int lqb = grp & 1, ks = grp >> 1;
            int r = lqb * 16 + (lane >> 2);
            int kb = ks * 16 + (lane & 3) * 2;
            uint4 v;
            v.x = pack_bf(s[kb][r],         s[kb + 1][r]);
            v.y = pack_bf(s[kb][r + 8],     s[kb + 1][r + 8]);
            v.z = pack_bf(s[kb + 8][r],     s[kb + 9][r]);
            v.w = pack_bf(s[kb + 8][r + 8], s[kb + 9][r + 8]);
            g_afrag[(bid - 256) * 2 + lqb][ks][lane] = v;
        }
    }
}

// ---------------- main kernel: 32 q/warp, 16-code chunks, distance-4 MMA chains --
// 16 warps: wg = wid>>2 (code quarter), wl = wid&3 (32-query m-block).
// 4 warps per quarter walk the SAME stream -> L1 serves 3/4 of B reads.
// MMA loops keep ks OUTERMOST: consecutive MMAs hit different accumulator
// chains (mi,nt), so same-chain dependency distance is 4 (vs 1 in R15).
__global__ void __launch_bounds__(512, 1) vq_mma_kernel() {
    const int tid  = threadIdx.x;
    const int lane = tid & 31;
    const int wid  = tid >> 5;
    const int wg   = wid >> 2;           // code quarter
    const int wl   = wid & 3;            // 32-query m-block
    const int q0   = blockIdx.x * MT + wl * 32;
    const int qb   = blockIdx.x * 8 + wl * 2;
    const int kc   = (lane & 3) * 2;
    const int rbase = q0 + (lane >> 2);

    uint4 af[2][4];
#pragma unroll
    for (int mi = 0; mi < 2; ++mi)
#pragma unroll
        for (int ks = 0; ks < 4; ++ks)
            af[mi][ks] = g_afrag[qb + mi][ks][lane];

    // chunk c, block nt, pair kp at bbase[c*128 + nt*64 + kp*32]
    const uint4*  bbase = &g_bfrag2[wg * (NQUART / 8)][0][lane];
    const float4* nbase_p = &g_nfrag[wg * (NQUART / 16)][lane];
    const int nbase = wg * NQUART;

    float runbest[4] = {FLT_MAX, FLT_MAX, FLT_MAX, FLT_MAX};

    // ---- warmup: chunk 0, min-only (ks-outermost ordering) ----
    {
        uint4 wb[2][2];                  // [nt][kp]
#pragma unroll
        for (int nt = 0; nt < 2; ++nt)
#pragma unroll
            for (int kp = 0; kp < 2; ++kp)
                wb[nt][kp] = bbase[nt * 64 + kp * 32];
        float4 nf = nbase_p[0];
        float acc[2][2][4];
#pragma unroll
        for (int mi = 0; mi < 2; ++mi)
#pragma unroll
            for (int nt = 0; nt < 2; ++nt)
#pragma unroll
                for (int e = 0; e < 4; ++e) acc[mi][nt][e] = 0.f;
#pragma unroll
        for (int kp = 0; kp < 2; ++kp) {
#pragma unroll
            for (int mi = 0; mi < 2; ++mi)
#pragma unroll
                for (int nt = 0; nt < 2; ++nt)
                    mma16816(acc[mi][nt], (const uint32_t*)&af[mi][kp * 2],
                             wb[nt][kp].x, wb[nt][kp].y);
#pragma unroll
            for (int mi = 0; mi < 2; ++mi)
#pragma unroll
                for (int nt = 0; nt < 2; ++nt)
                    mma16816(acc[mi][nt], (const uint32_t*)&af[mi][kp * 2 + 1],
                             wb[nt][kp].z, wb[nt][kp].w);
        }
#pragma unroll
        for (int mi = 0; mi < 2; ++mi)
#pragma unroll
            for (int rr = 0; rr < 2; ++rr) {
                float gm = fminf(
                    fminf(fmaf(-2.f, acc[mi][0][rr * 2],     nf.x),
                          fmaf(-2.f, acc[mi][0][rr * 2 + 1], nf.y)),
                    fminf(fmaf(-2.f, acc[mi][1][rr * 2],     nf.z),
                          fmaf(-2.f, acc[mi][1][rr * 2 + 1], nf.w)));
                runbest[mi * 2 + rr] = gm;
            }
#pragma unroll
        for (int s2 = 0; s2 < 4; ++s2) {
            runbest[s2] = fminf(runbest[s2], __shfl_xor_sync(0xFFFFFFFFu, runbest[s2], 1));
            runbest[s2] = fminf(runbest[s2], __shfl_xor_sync(0xFFFFFFFFu, runbest[s2], 2));
        }
    }

    // ---- pipelined main loop: ping-pong ring over ks-pairs ----
    uint4 ring[2][2];                    // [slot][nt]
#pragma unroll
    for (int nt = 0; nt < 2; ++nt)       // prologue: kp0(chunk0), L1-hot
        ring[0][nt] = bbase[nt * 64];

#pragma unroll 1
    for (int c = 0; c < NCHUNK_Q; ++c) {
        const uint4* bc  = bbase + c * 128;
        const uint4* bcn = (c + 1 < NCHUNK_Q) ? bc + 128 : bc;

        float acc[2][2][4];
#pragma unroll
        for (int mi = 0; mi < 2; ++mi)
#pragma unroll
            for (int nt = 0; nt < 2; ++nt)
#pragma unroll
                for (int e = 0; e < 4; ++e) acc[mi][nt][e] = 0.f;

        // phase A: prefetch kp1(c) -> slot1; load norms; MMA ks0 then ks1
#pragma unroll
        for (int nt = 0; nt < 2; ++nt) ring[1][nt] = bc[nt * 64 + 32];
        float4 nf = nbase_p[c * 32];
#pragma unroll
        for (int mi = 0; mi < 2; ++mi)
#pragma unroll
            for (int nt = 0; nt < 2; ++nt)
                mma16816(acc[mi][nt], (const uint32_t*)&af[mi][0],
                         ring[0][nt].x, ring[0][nt].y);
#pragma unroll
        for (int mi = 0; mi < 2; ++mi)
#pragma unroll
            for (int nt = 0; nt < 2; ++nt)
                mma16816(acc[mi][nt], (const uint32_t*)&af[mi][1],
                         ring[0][nt].z, ring[0][nt].w);

        // phase B: prefetch kp0(c+1) -> slot0; MMA ks2 then ks3
#pragma unroll
        for (int nt = 0; nt < 2; ++nt) ring[0][nt] = bcn[nt * 64];
#pragma unroll
        for (int mi = 0; mi < 2; ++mi)
#pragma unroll
            for (int nt = 0; nt < 2; ++nt)
                mma16816(acc[mi][nt], (const uint32_t*)&af[mi][2],
                         ring[1][nt].x, ring[1][nt].y);
#pragma unroll
        for (int mi = 0; mi < 2; ++mi)
#pragma unroll
            for (int nt = 0; nt < 2; ++nt)
                mma16816(acc[mi][nt], (const uint32_t*)&af[mi][3],
                         ring[1][nt].z, ring[1][nt].w);

        // ---- group-min epilogue (16 scores) ----
        const int cb = nbase + c * 16;
#pragma unroll
        for (int mi = 0; mi < 2; ++mi)
#pragma unroll
            for (int rr = 0; rr < 2; ++rr) {
                const int i = mi * 2 + rr;
                float s0 = fmaf(-2.f, acc[mi][0][rr * 2],     nf.x);
                float s1 = fmaf(-2.f, acc[mi][0][rr * 2 + 1], nf.y);
                float s2 = fmaf(-2.f, acc[mi][1][rr * 2],     nf.z);
                float s3 = fmaf(-2.f, acc[mi][1][rr * 2 + 1], nf.w);
                float gm = fminf(fminf(s0, s1), fminf(s2, s3));
                const float th = runbest[i] + MARGIN;
                if (gm < th) {                          // rare
                    const int q = rbase + mi * 16 + rr * 8;
                    if (s0 < th) {
                        int pos = atomicAdd(&g_ncand[q], 1);
                        if (pos < CAND_MAX) g_cand[q * CAND_MAX + pos] = cb + kc;
                    }
                    if (s1 < th) {
                        int pos = atomicAdd(&g_ncand[q], 1);
                        if (pos < CAND_MAX) g_cand[q * CAND_MAX + pos] = cb + kc + 1;
                    }
                    if (s2 < th) {
                        int pos = atomicAdd(&g_ncand[q], 1);
                        if (pos < CAND_MAX) g_cand[q * CAND_MAX + pos] = cb + 8 + kc;
                    }
                    if (s3 < th) {
                        int pos = atomicAdd(&g_ncand[q], 1);
                        if (pos < CAND_MAX) g_cand[q * CAND_MAX + pos] = cb + 8 + kc + 1;
                    }
                }
                runbest[i] = fminf(runbest[i], gm);
            }
#pragma unroll
        for (int s2 = 0; s2 < 4; ++s2) {
            runbest[s2] = fminf(runbest[s2], __shfl_xor_sync(0xFFFFFFFFu, runbest[s2], 1));
            runbest[s2] = fminf(runbest[s2], __shfl_xor_sync(0xFFFFFFFFu, runbest[s2], 2));
        }
    }
}

// ---------------- exact fp32 rescore + gather (candidate-per-lane) ----------------
__global__ void __launch_bounds__(256) rescore_kernel(float* __restrict__ out) {
    const int wid = threadIdx.x >> 5, lane = threadIdx.x & 31;
    const int q = blockIdx.x * 8 + wid;

    const float4* xr = (const float4*)(g_xq + (size_t)q * E_DIM);
    const int nc = g_ncand[q];

    float best = FLT_MAX;
    int bj = N_EMBED;

    if (nc <= CAND_MAX) {
        for (int base = 0; base < nc; base += 32) {
            int i = base + lane;
            float s = FLT_MAX;
            int j = N_EMBED;
            if (i < nc) {
                j = g_cand[q * CAND_MAX + i];
                const float4* er = (const float4*)(g_embT + (size_t)j * E_DIM);
                float p = 0.f;
#pragma unroll
                for (int t = 0; t < 16; ++t) {
                    float4 e = er[t], xx = xr[t];
                    p = fmaf(e.x, xx.x, p); p = fmaf(e.y, xx.y, p);
                    p = fmaf(e.z, xx.z, p); p = fmaf(e.w, xx.w, p);
                }
                s = fmaf(-2.f, p, g_norms[j]);
            }
            if (s < best || (s == best && j < bj)) { best = s; bj = j; }
        }
    } else {
        for (int j0 = 0; j0 < N_EMBED; j0 += 32) {     // overflow fallback (rare)
            int j = j0 + lane;
            const float4* er = (const float4*)(g_embT + (size_t)j * E_DIM);
            float p = 0.f;
#pragma unroll
            for (int t = 0; t < 16; ++t) {
                float4 e = er[t], xx = xr[t];
                p = fmaf(e.x, xx.x, p); p = fmaf(e.y, xx.y, p);
                p = fmaf(e.z, xx.z, p); p = fmaf(e.w, xx.w, p);
            }
            float s = fmaf(-2.f, p, g_norms[j]);
            if (s < best || (s == best && j < bj)) { best = s; bj = j; }
        }
    }

#pragma unroll
    for (int off = 16; off > 0; off >>= 1) {
        float os = __shfl_xor_sync(0xFFFFFFFFu, best, off);
        int   oj = __shfl_xor_sync(0xFFFFFFFFu, bj, off);
        if (os < best || (os == best && oj < bj)) { best = os; bj = oj; }
    }

    out[(size_t)q * E_DIM + lane]      = g_embT[(size_t)bj * E_DIM + lane];
    out[(size_t)q * E_DIM + 32 + lane] = g_embT[(size_t)bj * E_DIM + 32 + lane];
}

// ---------------- launch ----------------
extern "C" void kernel_launch(void* const* d_in, const int* in_sizes, int n_in,
                              void* d_out, int out_size) {
    const float* x     = (const float*)d_in[0];   // [16,64,32,32]
    const float* embed = (const float*)d_in[1];   // [64,8192]
    float* out = (float*)d_out;                   // [16,32,32,64]

    prep_kernel<<<768, 256>>>(x, embed);
    vq_mma_kernel<<<N_QUERY / MT, 512>>>();
    rescore_kernel<<<N_QUERY / 8, 256>>>(out);
}